// round 5
// baseline (speedup 1.0000x reference)
#include <cuda_runtime.h>
#include <math.h>

// Problem constants
#define DM   768
#define BSZ  2
#define NSEQ 2048
#define NH   12
#define DK   64
#define ROWS (BSZ*NSEQ)          // 4096
#define SLOT ((size_t)ROWS*DM)   // 3,145,728 floats

__device__ float g_scratch[10 * SLOT];

// ---------------- TF32 mma helpers ----------------
__device__ __forceinline__ unsigned f2tf(float f) {
    unsigned u;
    asm("cvt.rna.tf32.f32 %0, %1;" : "=r"(u) : "f"(f));
    return u;
}
__device__ __forceinline__ void mma_tf32(
    float& c0, float& c1, float& c2, float& c3,
    unsigned a0, unsigned a1, unsigned a2, unsigned a3,
    unsigned b0, unsigned b1)
{
    asm("mma.sync.aligned.m16n8k8.row.col.f32.tf32.tf32.f32 "
        "{%0,%1,%2,%3},{%4,%5,%6,%7},{%8,%9},{%0,%1,%2,%3};"
        : "+f"(c0), "+f"(c1), "+f"(c2), "+f"(c3)
        : "r"(a0), "r"(a1), "r"(a2), "r"(a3), "r"(b0), "r"(b1));
}

// ---------------------------------------------------------------------------
// LayerNorm: one block per row; row < ROWS -> rgb w/ ln0, else ir w/ ln1
// ---------------------------------------------------------------------------
__global__ __launch_bounds__(256) void ln_kernel(
    const float* __restrict__ rgb, const float* __restrict__ ir,
    const float* __restrict__ w0, const float* __restrict__ b0,
    const float* __restrict__ w1, const float* __restrict__ b1,
    float* __restrict__ out_rgbn, float* __restrict__ out_irn)
{
    int row = blockIdx.x;
    const float* x; float* y; const float* w; const float* b;
    if (row < ROWS) { x = rgb + (size_t)row*DM; y = out_rgbn + (size_t)row*DM; w = w0; b = b0; }
    else { row -= ROWS; x = ir + (size_t)row*DM; y = out_irn + (size_t)row*DM; w = w1; b = b1; }

    int t = threadIdx.x;
    float v0 = x[t], v1 = x[t+256], v2 = x[t+512];
    float s  = v0+v1+v2;
    float sq = v0*v0 + v1*v1 + v2*v2;

    #pragma unroll
    for (int o = 16; o > 0; o >>= 1) {
        s  += __shfl_xor_sync(0xffffffffu, s,  o);
        sq += __shfl_xor_sync(0xffffffffu, sq, o);
    }
    __shared__ float shs[8], shq[8];
    int warp = t >> 5, lane = t & 31;
    if (lane == 0) { shs[warp] = s; shq[warp] = sq; }
    __syncthreads();
    float ts = 0.f, tq = 0.f;
    #pragma unroll
    for (int i = 0; i < 8; i++) { ts += shs[i]; tq += shq[i]; }

    const float inv = 1.0f / (float)DM;
    float mean = ts * inv;
    float var  = tq * inv - mean*mean;
    float rstd = rsqrtf(var + 1e-5f);

    y[t]     = (v0 - mean)*rstd*w[t]     + b[t];
    y[t+256] = (v1 - mean)*rstd*w[t+256] + b[t+256];
    y[t+512] = (v2 - mean)*rstd*w[t+512] + b[t+512];
}

// ---------------------------------------------------------------------------
// Batched TF32 tensor-core GEMM + bias, DOUBLE-BUFFERED smem.
// BM=128 BN=128 BK=16, 256 threads = 8 warps (2m x 4n), warp tile 64x32.
// One __syncthreads per k-step; global prefetch overlaps mma.
// ---------------------------------------------------------------------------
#define BM 128
#define BN 128
#define BK 16

struct GemmBatch {
    const float* A[6];
    const float* W[6];
    const float* bias[6];
    float*       C[6];
};

__global__ __launch_bounds__(256, 2) void gemm_tf32(GemmBatch gb)
{
    __shared__ unsigned As[2][BM][BK+4];   // [m][k]
    __shared__ unsigned Bs[2][BN][BK+4];   // [n][k]

    int z = blockIdx.z;
    const float* A    = gb.A[z];
    const float* W    = gb.W[z];
    const float* bias = gb.bias[z];
    float*       C    = gb.C[z];

    int t    = threadIdx.x;
    int warp = t >> 5, lane = t & 31;
    int g    = lane >> 2;     // groupID 0..7
    int q4   = lane & 3;      // threadID_in_group 0..3
    int wm   = warp & 1;      // 2 m-warps  (64 rows each)
    int wn   = warp >> 1;     // 4 n-warps  (32 cols each)
    int bx   = blockIdx.x, by = blockIdx.y;

    int s_arow = t >> 2;
    int s_akq  = (t & 3) * 4;
    int s_bk   = t & 15;
    int s_bn4  = (t >> 4) * 4;

    const float* Aptr0 = A + (size_t)(by*BM + s_arow)      * DM + s_akq;
    const float* Aptr1 = A + (size_t)(by*BM + s_arow + 64) * DM + s_akq;
    const float* Wptr  = W + (size_t)s_bk * DM + bx*BN + s_bn4;

    float acc[4][4][4];
    #pragma unroll
    for (int mt = 0; mt < 4; mt++)
        #pragma unroll
        for (int nt = 0; nt < 4; nt++)
            #pragma unroll
            for (int c = 0; c < 4; c++) acc[mt][nt][c] = 0.f;

    float4 pa0 = *(const float4*)(Aptr0);
    float4 pa1 = *(const float4*)(Aptr1);
    float4 pb0 = *(const float4*)(Wptr);
    float4 pb1 = *(const float4*)(Wptr + 64);

    // stage buffer 0
    *(uint4*)&As[0][s_arow][s_akq] =
        make_uint4(f2tf(pa0.x), f2tf(pa0.y), f2tf(pa0.z), f2tf(pa0.w));
    *(uint4*)&As[0][s_arow+64][s_akq] =
        make_uint4(f2tf(pa1.x), f2tf(pa1.y), f2tf(pa1.z), f2tf(pa1.w));
    Bs[0][s_bn4+0][s_bk] = f2tf(pb0.x);
    Bs[0][s_bn4+1][s_bk] = f2tf(pb0.y);
    Bs[0][s_bn4+2][s_bk] = f2tf(pb0.z);
    Bs[0][s_bn4+3][s_bk] = f2tf(pb0.w);
    Bs[0][s_bn4+64][s_bk] = f2tf(pb1.x);
    Bs[0][s_bn4+65][s_bk] = f2tf(pb1.y);
    Bs[0][s_bn4+66][s_bk] = f2tf(pb1.z);
    Bs[0][s_bn4+67][s_bk] = f2tf(pb1.w);
    __syncthreads();

    int buf = 0;
    for (int k0 = 0; k0 < DM; k0 += BK) {
        bool has_next = (k0 + BK < DM);
        if (has_next) {
            Aptr0 += BK; Aptr1 += BK;
            Wptr  += (size_t)BK * DM;
            pa0 = *(const float4*)(Aptr0);
            pa1 = *(const float4*)(Aptr1);
            pb0 = *(const float4*)(Wptr);
            pb1 = *(const float4*)(Wptr + 64);
        }

        #pragma unroll
        for (int kk = 0; kk < 2; kk++) {
            int kc = kk*8 + q4;
            unsigned af[4][4], bf[4][2];
            #pragma unroll
            for (int mt = 0; mt < 4; mt++) {
                int mr = wm*64 + mt*16 + g;
                af[mt][0] = As[buf][mr][kc];
                af[mt][1] = As[buf][mr+8][kc];
                af[mt][2] = As[buf][mr][kc+4];
                af[mt][3] = As[buf][mr+8][kc+4];
            }
            #pragma unroll
            for (int nt = 0; nt < 4; nt++) {
                int nc = wn*32 + nt*8 + g;
                bf[nt][0] = Bs[buf][nc][kc];
                bf[nt][1] = Bs[buf][nc][kc+4];
            }
            #pragma unroll
            for (int mt = 0; mt < 4; mt++)
                #pragma unroll
                for (int nt = 0; nt < 4; nt++)
                    mma_tf32(acc[mt][nt][0], acc[mt][nt][1], acc[mt][nt][2], acc[mt][nt][3],
                             af[mt][0], af[mt][1], af[mt][2], af[mt][3],
                             bf[nt][0], bf[nt][1]);
        }

        if (has_next) {
            int nb = buf ^ 1;
            *(uint4*)&As[nb][s_arow][s_akq] =
                make_uint4(f2tf(pa0.x), f2tf(pa0.y), f2tf(pa0.z), f2tf(pa0.w));
            *(uint4*)&As[nb][s_arow+64][s_akq] =
                make_uint4(f2tf(pa1.x), f2tf(pa1.y), f2tf(pa1.z), f2tf(pa1.w));
            Bs[nb][s_bn4+0][s_bk] = f2tf(pb0.x);
            Bs[nb][s_bn4+1][s_bk] = f2tf(pb0.y);
            Bs[nb][s_bn4+2][s_bk] = f2tf(pb0.z);
            Bs[nb][s_bn4+3][s_bk] = f2tf(pb0.w);
            Bs[nb][s_bn4+64][s_bk] = f2tf(pb1.x);
            Bs[nb][s_bn4+65][s_bk] = f2tf(pb1.y);
            Bs[nb][s_bn4+66][s_bk] = f2tf(pb1.z);
            Bs[nb][s_bn4+67][s_bk] = f2tf(pb1.w);
        }
        __syncthreads();
        buf ^= 1;
    }

    #pragma unroll
    for (int mt = 0; mt < 4; mt++) {
        #pragma unroll
        for (int nt = 0; nt < 4; nt++) {
            int row0 = by*BM + wm*64 + mt*16 + g;
            int col  = bx*BN + wn*32 + nt*8 + 2*q4;
            float2 bb = *(const float2*)(bias + col);
            float2 o0 = make_float2(acc[mt][nt][0] + bb.x, acc[mt][nt][1] + bb.y);
            float2 o1 = make_float2(acc[mt][nt][2] + bb.x, acc[mt][nt][3] + bb.y);
            *(float2*)(C + (size_t)row0*DM + col)     = o0;
            *(float2*)(C + (size_t)(row0+8)*DM + col) = o1;
        }
    }
}

// ---------------------------------------------------------------------------
// TF32 tensor-core flash attention, Br=128, 512 threads = 16 warps.
// grid (NSEQ/128, NH, 4): z = which*2 + b.
// Warp grid: wm = warp>>1 (8 x 16 rows), wn = warp&1 (2 x 32 cols).
// Q fragments register-resident; next K/V tile prefetched into registers
// right after the staging sync. P (128x64) lives in KsPs (q-rows 0..63)
// + Ps2 (q-rows 64..127). Sync ordering identical to the proven R4 kernel.
// ---------------------------------------------------------------------------
#define ABR 128
#define ABC 64
#define ATHREADS 512
__global__ __launch_bounds__(ATHREADS) void attn_tf32(
    const float* __restrict__ qir,  const float* __restrict__ kvis, const float* __restrict__ vvis,
    const float* __restrict__ qvis, const float* __restrict__ kir,  const float* __restrict__ vir,
    float* __restrict__ att0, float* __restrict__ att1)
{
    __shared__ unsigned KsPs[ABC][68];  // K [key][d] during S ; P q-rows 0..63 during PV
    __shared__ unsigned Ps2[ABC][68];   // P q-rows 64..127 during PV
    __shared__ unsigned Vs[ABC][68];    // V [key][d]
    __shared__ float redM[2][ABR];
    __shared__ float redS[2][ABR];

    int z = blockIdx.z;
    int which = z >> 1;
    int b = z & 1;
    const float *Qg, *Kg, *Vg; float* Og;
    if (which == 0) { Qg = qir;  Kg = kvis; Vg = vvis; Og = att0; }
    else            { Qg = qvis; Kg = kir;  Vg = vir;  Og = att1; }

    int t    = threadIdx.x;
    int warp = t >> 5, lane = t & 31;
    int g    = lane >> 2;
    int q4   = lane & 3;
    int wm   = warp >> 1;           // 0..7 : q rows [wm*16, +16)
    int wn   = warp & 1;            // 0..1 : cols   [wn*32, +32)
    int R0   = wm*16 + g;           // 0..127
    int R1   = R0 + 8;

    int h    = blockIdx.y;
    int qblk = blockIdx.x;
    const size_t headoff = (size_t)h * DK;
    const size_t batoff  = (size_t)b * NSEQ;

    // ---- Q fragments in registers (scaled, tf32) ----
    unsigned qf[8][4];
    {
        const float* qbase = Qg + (batoff + qblk*ABR)*DM + headoff;
        const float scale = 0.125f;
        #pragma unroll
        for (int kk = 0; kk < 8; kk++) {
            int c = kk*8 + q4;
            qf[kk][0] = f2tf(qbase[(size_t)R0*DM + c]     * scale);
            qf[kk][1] = f2tf(qbase[(size_t)R1*DM + c]     * scale);
            qf[kk][2] = f2tf(qbase[(size_t)R0*DM + c + 4] * scale);
            qf[kk][3] = f2tf(qbase[(size_t)R1*DM + c + 4] * scale);
        }
    }

    // staging geometry: 64 rows x 16 d4-granules = 1024 granules, 512 threads
    int st_row0 = t >> 4;             // 0..31
    int st_d4   = (t & 15) * 4;
    const float* kp0 = Kg + (batoff + st_row0)*DM      + headoff + st_d4;
    const float* kp1 = Kg + (batoff + st_row0 + 32)*DM + headoff + st_d4;
    const float* vp0 = Vg + (batoff + st_row0)*DM      + headoff + st_d4;
    const float* vp1 = Vg + (batoff + st_row0 + 32)*DM + headoff + st_d4;

    float m0 = -INFINITY, m1 = -INFINITY, l0 = 0.f, l1 = 0.f;
    float o[4][4];
    #pragma unroll
    for (int nt = 0; nt < 4; nt++)
        #pragma unroll
        for (int c = 0; c < 4; c++) o[nt][c] = 0.f;

    // P-buffer row mapping (constant per thread)
    unsigned (*P0)[68] = (R0 < 64) ? KsPs : Ps2;
    unsigned (*P1)[68] = (R1 < 64) ? KsPs : Ps2;
    int r0 = R0 & 63;
    int r1 = R1 & 63;

    // initial prefetch of tile 0
    float4 kr0 = *(const float4*)kp0;
    float4 kr1 = *(const float4*)kp1;
    float4 vr0 = *(const float4*)vp0;
    float4 vr1 = *(const float4*)vp1;

    for (int kt = 0; kt < NSEQ/ABC; kt++) {
        // ---- stage K, V from prefetched registers ----
        *(uint4*)&KsPs[st_row0][st_d4]    = make_uint4(f2tf(kr0.x), f2tf(kr0.y), f2tf(kr0.z), f2tf(kr0.w));
        *(uint4*)&KsPs[st_row0+32][st_d4] = make_uint4(f2tf(kr1.x), f2tf(kr1.y), f2tf(kr1.z), f2tf(kr1.w));
        *(uint4*)&Vs[st_row0][st_d4]      = make_uint4(f2tf(vr0.x), f2tf(vr0.y), f2tf(vr0.z), f2tf(vr0.w));
        *(uint4*)&Vs[st_row0+32][st_d4]   = make_uint4(f2tf(vr1.x), f2tf(vr1.y), f2tf(vr1.z), f2tf(vr1.w));
        __syncthreads();

        // ---- prefetch next tile (hidden behind S + softmax + PV) ----
        if (kt + 1 < NSEQ/ABC) {
            kp0 += (size_t)ABC*DM; kp1 += (size_t)ABC*DM;
            vp0 += (size_t)ABC*DM; vp1 += (size_t)ABC*DM;
            kr0 = *(const float4*)kp0;
            kr1 = *(const float4*)kp1;
            vr0 = *(const float4*)vp0;
            vr1 = *(const float4*)vp1;
        }

        // ---- S = Q @ K^T ----
        float s[4][4];
        #pragma unroll
        for (int nt = 0; nt < 4; nt++)
            #pragma unroll
            for (int c = 0; c < 4; c++) s[nt][c] = 0.f;

        #pragma unroll
        for (int kk = 0; kk < 8; kk++) {
            int kc = kk*8 + q4;
            unsigned bf[4][2];
            #pragma unroll
            for (int nt = 0; nt < 4; nt++) {
                int nc = wn*32 + nt*8 + g;
                bf[nt][0] = KsPs[nc][kc];
                bf[nt][1] = KsPs[nc][kc+4];
            }
            #pragma unroll
            for (int nt = 0; nt < 4; nt++)
                mma_tf32(s[nt][0], s[nt][1], s[nt][2], s[nt][3],
                         qf[kk][0], qf[kk][1], qf[kk][2], qf[kk][3],
                         bf[nt][0], bf[nt][1]);
        }

        // ---- row max (quad shfl + cross-warp smem) ----
        float mx0 = -INFINITY, mx1 = -INFINITY;
        #pragma unroll
        for (int nt = 0; nt < 4; nt++) {
            mx0 = fmaxf(mx0, fmaxf(s[nt][0], s[nt][1]));
            mx1 = fmaxf(mx1, fmaxf(s[nt][2], s[nt][3]));
        }
        mx0 = fmaxf(mx0, __shfl_xor_sync(0xffffffffu, mx0, 1));
        mx0 = fmaxf(mx0, __shfl_xor_sync(0xffffffffu, mx0, 2));
        mx1 = fmaxf(mx1, __shfl_xor_sync(0xffffffffu, mx1, 1));
        mx1 = fmaxf(mx1, __shfl_xor_sync(0xffffffffu, mx1, 2));
        if (q4 == 0) { redM[wn][R0] = mx0; redM[wn][R1] = mx1; }
        __syncthreads();   // all K reads done; redM visible

        float nm0 = fmaxf(m0, fmaxf(redM[0][R0], redM[1][R0]));
        float nm1 = fmaxf(m1, fmaxf(redM[0][R1], redM[1][R1]));
        float c0 = __expf(m0 - nm0);
        float c1 = __expf(m1 - nm1);
        m0 = nm0; m1 = nm1;

        float ps0 = 0.f, ps1 = 0.f;
        #pragma unroll
        for (int nt = 0; nt < 4; nt++) {
            s[nt][0] = __expf(s[nt][0] - nm0);
            s[nt][1] = __expf(s[nt][1] - nm0);
            s[nt][2] = __expf(s[nt][2] - nm1);
            s[nt][3] = __expf(s[nt][3] - nm1);
            ps0 += s[nt][0] + s[nt][1];
            ps1 += s[nt][2] + s[nt][3];
        }
        ps0 += __shfl_xor_sync(0xffffffffu, ps0, 1);
        ps0 += __shfl_xor_sync(0xffffffffu, ps0, 2);
        ps1 += __shfl_xor_sync(0xffffffffu, ps1, 1);
        ps1 += __shfl_xor_sync(0xffffffffu, ps1, 2);
        if (q4 == 0) { redS[wn][R0] = ps0; redS[wn][R1] = ps1; }

        // ---- write P (K buffer is dead now) ----
        #pragma unroll
        for (int nt = 0; nt < 4; nt++) {
            int col = wn*32 + nt*8 + 2*q4;
            *(uint2*)&P0[r0][col] = make_uint2(f2tf(s[nt][0]), f2tf(s[nt][1]));
            *(uint2*)&P1[r1][col] = make_uint2(f2tf(s[nt][2]), f2tf(s[nt][3]));
        }
        // rescale O
        #pragma unroll
        for (int nt = 0; nt < 4; nt++) {
            o[nt][0] *= c0; o[nt][1] *= c0;
            o[nt][2] *= c1; o[nt][3] *= c1;
        }
        __syncthreads();   // P + redS visible

        l0 = l0*c0 + redS[0][R0] + redS[1][R0];
        l1 = l1*c1 + redS[0][R1] + redS[1][R1];

        // ---- O += P @ V ----
        #pragma unroll
        for (int kk = 0; kk < 8; kk++) {
            int kc = kk*8 + q4;
            unsigned af[4];
            af[0] = P0[r0][kc];
            af[1] = P1[r1][kc];
            af[2] = P0[r0][kc+4];
            af[3] = P1[r1][kc+4];
            #pragma unroll
            for (int nt = 0; nt < 4; nt++) {
                int dc = wn*32 + nt*8 + g;
                unsigned b0 = Vs[kk*8 + q4][dc];
                unsigned b1 = Vs[kk*8 + q4 + 4][dc];
                mma_tf32(o[nt][0], o[nt][1], o[nt][2], o[nt][3],
                         af[0], af[1], af[2], af[3], b0, b1);
            }
        }
        __syncthreads();   // PV done before next tile overwrites buffers
    }

    // ---- epilogue ----
    float i0 = 1.0f / l0;
    float i1 = 1.0f / l1;
    #pragma unroll
    for (int nt = 0; nt < 4; nt++) {
        size_t col = headoff + wn*32 + nt*8 + 2*q4;
        float* p0 = Og + (batoff + qblk*ABR + R0)*DM + col;
        float* p1 = Og + (batoff + qblk*ABR + R1)*DM + col;
        *(float2*)p0 = make_float2(o[nt][0]*i0, o[nt][1]*i0);
        *(float2*)p1 = make_float2(o[nt][2]*i1, o[nt][3]*i1);
    }
}

// ---------------------------------------------------------------------------
// Launch
// ---------------------------------------------------------------------------
extern "C" void kernel_launch(void* const* d_in, const int* in_sizes, int n_in,
                              void* d_out, int out_size)
{
    const float* rgb    = (const float*)d_in[0];
    const float* ir     = (const float*)d_in[1];
    const float* ln0_w  = (const float*)d_in[2];
    const float* ln0_b  = (const float*)d_in[3];
    const float* ln1_w  = (const float*)d_in[4];
    const float* ln1_b  = (const float*)d_in[5];
    const float* Wq_vis = (const float*)d_in[6];
    const float* bq_vis = (const float*)d_in[7];
    const float* Wk_vis = (const float*)d_in[8];
    const float* bk_vis = (const float*)d_in[9];
    const float* Wq_ir  = (const float*)d_in[10];
    const float* bq_ir  = (const float*)d_in[11];
    const float* Wk_ir  = (const float*)d_in[12];
    const float* bk_ir  = (const float*)d_in[13];
    const float* Wv_vis = (const float*)d_in[14];
    const float* bv_vis = (const float*)d_in[15];
    const float* Wv_ir  = (const float*)d_in[16];
    const float* bv_ir  = (const float*)d_in[17];
    const float* Wo_vis = (const float*)d_in[18];
    const float* bo_vis = (const float*)d_in[19];
    const float* Wo_ir  = (const float*)d_in[20];
    const float* bo_ir  = (const float*)d_in[21];
    float* out = (float*)d_out;

    float* scr = nullptr;
    cudaGetSymbolAddress((void**)&scr, g_scratch);
    float* rgbn = scr + 0*SLOT;
    float* irn  = scr + 1*SLOT;
    float* qvis = scr + 2*SLOT;
    float* kvis = scr + 3*SLOT;
    float* vvis = scr + 4*SLOT;
    float* qir  = scr + 5*SLOT;
    float* kir  = scr + 6*SLOT;
    float* vir  = scr + 7*SLOT;
    float* att0 = scr + 8*SLOT;
    float* att1 = scr + 9*SLOT;

    // 1. LayerNorms
    ln_kernel<<<2*ROWS, 256>>>(rgb, ir, ln0_w, ln0_b, ln1_w, ln1_b, rgbn, irn);

    // 2. All six projections in one batched launch
    GemmBatch proj;
    proj.A[0]=rgbn; proj.W[0]=Wq_vis; proj.bias[0]=bq_vis; proj.C[0]=qvis;
    proj.A[1]=rgbn; proj.W[1]=Wk_vis; proj.bias[1]=bk_vis; proj.C[1]=kvis;
    proj.A[2]=rgbn; proj.W[2]=Wv_vis; proj.bias[2]=bv_vis; proj.C[2]=vvis;
    proj.A[3]=irn;  proj.W[3]=Wq_ir;  proj.bias[3]=bq_ir;  proj.C[3]=qir;
    proj.A[4]=irn;  proj.W[4]=Wk_ir;  proj.bias[4]=bk_ir;  proj.C[4]=kir;
    proj.A[5]=irn;  proj.W[5]=Wv_ir;  proj.bias[5]=bv_ir;  proj.C[5]=vir;
    dim3 pgrid(DM/BN, ROWS/BM, 6);   // (6, 32, 6)
    gemm_tf32<<<pgrid, 256>>>(proj);

    // 3. Both cross-attentions in one launch
    dim3 agrid(NSEQ/ABR, NH, 4);     // (16, 12, 4)
    attn_tf32<<<agrid, ATHREADS>>>(qir, kvis, vvis, qvis, kir, vir, att0, att1);

    // 4. Output projections straight into d_out (out_vis then out_ir)
    GemmBatch op;
    op.A[0]=att0; op.W[0]=Wo_vis; op.bias[0]=bo_vis; op.C[0]=out;
    op.A[1]=att1; op.W[1]=Wo_ir;  op.bias[1]=bo_ir;  op.C[1]=out + SLOT;
    for (int i = 2; i < 6; i++) { op.A[i]=att0; op.W[i]=Wo_vis; op.bias[i]=bo_vis; op.C[i]=out; }
    dim3 ogrid(DM/BN, ROWS/BM, 2);   // (6, 32, 2)
    gemm_tf32<<<ogrid, 256>>>(op);
}